// round 1
// baseline (speedup 1.0000x reference)
#include <cuda_runtime.h>

#define N_NODES   50000
#define N_EDGES   800000
#define D_FEAT    128
#define HIDDEN    256
#define N_CLASSES 2

// ---------------- scratch (static device globals; no runtime allocation) ----
__device__ int   g_deg[N_NODES];
__device__ int   g_rowptr[N_NODES + 1];
__device__ int   g_cursor[N_NODES];
__device__ float g_invdeg[N_NODES];
__device__ int   g_nbr[N_EDGES];
__device__ float g_mean[(size_t)N_NODES * HIDDEN];  // layer1: stride 128; layer2: stride 256

// ---------------- CSR build ------------------------------------------------
__global__ void k_zero_deg() {
    int i = blockIdx.x * blockDim.x + threadIdx.x;
    if (i < N_NODES) g_deg[i] = 0;
}

__global__ void k_hist(const int* __restrict__ dst) {
    int e = blockIdx.x * blockDim.x + threadIdx.x;
    if (e < N_EDGES) atomicAdd(&g_deg[dst[e]], 1);
}

// single block, 1024 threads: exclusive scan of degrees -> rowptr/cursor, invdeg
__global__ void k_scan() {
    __shared__ int warp_tot[32];
    __shared__ int s_carry;
    int tid  = threadIdx.x;
    int lane = tid & 31;
    int wid  = tid >> 5;
    if (tid == 0) s_carry = 0;
    __syncthreads();
    for (int base = 0; base < N_NODES; base += 1024) {
        int i = base + tid;
        int v = (i < N_NODES) ? g_deg[i] : 0;
        int xv = v;
#pragma unroll
        for (int o = 1; o < 32; o <<= 1) {
            int t = __shfl_up_sync(0xffffffffu, xv, o);
            if (lane >= o) xv += t;
        }
        if (lane == 31) warp_tot[wid] = xv;
        __syncthreads();
        if (wid == 0) {
            int w = warp_tot[lane];
#pragma unroll
            for (int o = 1; o < 32; o <<= 1) {
                int t = __shfl_up_sync(0xffffffffu, w, o);
                if (lane >= o) w += t;
            }
            warp_tot[lane] = w;  // inclusive over warp totals
        }
        __syncthreads();
        int warp_off = (wid > 0) ? warp_tot[wid - 1] : 0;
        int excl = xv - v + warp_off + s_carry;
        if (i < N_NODES) {
            g_rowptr[i] = excl;
            g_cursor[i] = excl;
            g_invdeg[i] = 1.0f / (float)(v > 0 ? v : 1);
        }
        __syncthreads();
        if (tid == 1023) s_carry += warp_tot[31];
        __syncthreads();
    }
    if (threadIdx.x == 0) g_rowptr[N_NODES] = s_carry;
}

__global__ void k_scatter(const int* __restrict__ src, const int* __restrict__ dst) {
    int e = blockIdx.x * blockDim.x + threadIdx.x;
    if (e < N_EDGES) {
        int d   = dst[e];
        int pos = atomicAdd(&g_cursor[d], 1);
        g_nbr[pos] = src[e];
    }
}

// ---------------- layer-1 mean aggregation (warp per node, 128 feats) -------
__global__ void k_agg1(const float* __restrict__ x) {
    int warp = (blockIdx.x * blockDim.x + threadIdx.x) >> 5;
    int lane = threadIdx.x & 31;
    if (warp >= N_NODES) return;
    int beg = g_rowptr[warp], end = g_rowptr[warp + 1];
    float4 acc = make_float4(0.f, 0.f, 0.f, 0.f);
    for (int j = beg; j < end; j++) {
        int s = g_nbr[j];
        float4 v = *(const float4*)(x + (size_t)s * D_FEAT + lane * 4);
        acc.x += v.x; acc.y += v.y; acc.z += v.z; acc.w += v.w;
    }
    float id = g_invdeg[warp];
    acc.x *= id; acc.y *= id; acc.z *= id; acc.w *= id;
    *(float4*)(g_mean + (size_t)warp * D_FEAT + lane * 4) = acc;
}

// ---------------- layer-2 mean aggregation (warp per node, 256 feats) -------
__global__ void k_agg2(const float* __restrict__ emb) {
    int warp = (blockIdx.x * blockDim.x + threadIdx.x) >> 5;
    int lane = threadIdx.x & 31;
    if (warp >= N_NODES) return;
    int beg = g_rowptr[warp], end = g_rowptr[warp + 1];
    float4 a0 = make_float4(0.f, 0.f, 0.f, 0.f);
    float4 a1 = make_float4(0.f, 0.f, 0.f, 0.f);
    for (int j = beg; j < end; j++) {
        int s = g_nbr[j];
        const float* r = emb + (size_t)s * HIDDEN;
        float4 v0 = *(const float4*)(r + lane * 4);
        float4 v1 = *(const float4*)(r + 128 + lane * 4);
        a0.x += v0.x; a0.y += v0.y; a0.z += v0.z; a0.w += v0.w;
        a1.x += v1.x; a1.y += v1.y; a1.z += v1.z; a1.w += v1.w;
    }
    float id = g_invdeg[warp];
    a0.x *= id; a0.y *= id; a0.z *= id; a0.w *= id;
    a1.x *= id; a1.y *= id; a1.z *= id; a1.w *= id;
    float* o = g_mean + (size_t)warp * HIDDEN;
    *(float4*)(o + lane * 4)       = a0;
    *(float4*)(o + 128 + lane * 4) = a1;
}

// ---------------- layer-1 fused GEMM: h = relu(mean@W1l + x@W1r + b1) -------
// block tile 64x64, K-chunks of 64, 256 threads, 4x4 microtile
__global__ void k_gemm1(const float* __restrict__ x,
                        const float* __restrict__ W1l,
                        const float* __restrict__ W1r,
                        const float* __restrict__ b1,
                        float* __restrict__ h) {
    __shared__ float As[64][64];
    __shared__ float Bs[64][64];
    int tid = threadIdx.x;
    int tx  = tid & 15;      // col group
    int ty  = tid >> 4;      // row group
    int m0  = blockIdx.x * 64;
    int n0  = blockIdx.y * 64;

    float acc[4][4];
#pragma unroll
    for (int i = 0; i < 4; i++)
#pragma unroll
        for (int j = 0; j < 4; j++) acc[i][j] = 0.f;

#pragma unroll
    for (int chunk = 0; chunk < 2; chunk++) {
        const float* A = chunk ? x : g_mean;     // [N][128]
        const float* B = chunk ? W1r : W1l;      // [128][256]
#pragma unroll
        for (int kk = 0; kk < 2; kk++) {
            // load A tile: 64 rows x 64 cols (k offset kk*64)
#pragma unroll
            for (int i = 0; i < 4; i++) {
                int idx = i * 256 + tid;         // float4 index, 1024 total
                int r   = idx >> 4;              // /16
                int c4  = idx & 15;
                int mg  = m0 + r;
                float4 v = (mg < N_NODES)
                    ? *(const float4*)(A + (size_t)mg * 128 + kk * 64 + c4 * 4)
                    : make_float4(0.f, 0.f, 0.f, 0.f);
                *(float4*)(&As[r][c4 * 4]) = v;
            }
            // load B tile: 64 k-rows x 64 n-cols
#pragma unroll
            for (int i = 0; i < 4; i++) {
                int idx = i * 256 + tid;
                int k   = idx >> 4;
                int n4  = idx & 15;
                float4 v = *(const float4*)(B + (size_t)(kk * 64 + k) * 256 + n0 + n4 * 4);
                *(float4*)(&Bs[k][n4 * 4]) = v;
            }
            __syncthreads();
#pragma unroll 8
            for (int k = 0; k < 64; k++) {
                float4 b = *(float4*)(&Bs[k][tx * 4]);
                float a0 = As[ty * 4 + 0][k];
                float a1 = As[ty * 4 + 1][k];
                float a2 = As[ty * 4 + 2][k];
                float a3 = As[ty * 4 + 3][k];
                acc[0][0] += a0 * b.x; acc[0][1] += a0 * b.y; acc[0][2] += a0 * b.z; acc[0][3] += a0 * b.w;
                acc[1][0] += a1 * b.x; acc[1][1] += a1 * b.y; acc[1][2] += a1 * b.z; acc[1][3] += a1 * b.w;
                acc[2][0] += a2 * b.x; acc[2][1] += a2 * b.y; acc[2][2] += a2 * b.z; acc[2][3] += a2 * b.w;
                acc[3][0] += a3 * b.x; acc[3][1] += a3 * b.y; acc[3][2] += a3 * b.z; acc[3][3] += a3 * b.w;
            }
            __syncthreads();
        }
    }
    float4 bias = *(const float4*)(b1 + n0 + tx * 4);
#pragma unroll
    for (int r = 0; r < 4; r++) {
        int mg = m0 + ty * 4 + r;
        if (mg < N_NODES) {
            float4 o;
            o.x = fmaxf(acc[r][0] + bias.x, 0.f);
            o.y = fmaxf(acc[r][1] + bias.y, 0.f);
            o.z = fmaxf(acc[r][2] + bias.z, 0.f);
            o.w = fmaxf(acc[r][3] + bias.w, 0.f);
            *(float4*)(h + (size_t)mg * HIDDEN + n0 + tx * 4) = o;
        }
    }
}

// ---------------- layer-2: out = sigmoid(mean2@W2l + h@W2r + b2) ------------
__global__ void k_out(const float* __restrict__ W2l,
                      const float* __restrict__ W2r,
                      const float* __restrict__ b2,
                      const float* __restrict__ emb,
                      float* __restrict__ out) {
    __shared__ float swl[HIDDEN * 2];
    __shared__ float swr[HIDDEN * 2];
    int tid = threadIdx.x;
    for (int i = tid; i < HIDDEN * 2; i += blockDim.x) {
        swl[i] = W2l[i];
        swr[i] = W2r[i];
    }
    __syncthreads();
    int warp = (blockIdx.x * blockDim.x + tid) >> 5;
    int lane = tid & 31;
    if (warp >= N_NODES) return;
    const float* m  = g_mean + (size_t)warp * HIDDEN;
    const float* hh = emb + (size_t)warp * HIDDEN;
    float acc0 = 0.f, acc1 = 0.f;
#pragma unroll
    for (int j = 0; j < 2; j++) {
        int k0 = lane * 8 + j * 4;
        float4 mv = *(const float4*)(m + k0);
        float4 hv = *(const float4*)(hh + k0);
        acc0 += mv.x * swl[(k0 + 0) * 2] + mv.y * swl[(k0 + 1) * 2]
              + mv.z * swl[(k0 + 2) * 2] + mv.w * swl[(k0 + 3) * 2];
        acc0 += hv.x * swr[(k0 + 0) * 2] + hv.y * swr[(k0 + 1) * 2]
              + hv.z * swr[(k0 + 2) * 2] + hv.w * swr[(k0 + 3) * 2];
        acc1 += mv.x * swl[(k0 + 0) * 2 + 1] + mv.y * swl[(k0 + 1) * 2 + 1]
              + mv.z * swl[(k0 + 2) * 2 + 1] + mv.w * swl[(k0 + 3) * 2 + 1];
        acc1 += hv.x * swr[(k0 + 0) * 2 + 1] + hv.y * swr[(k0 + 1) * 2 + 1]
              + hv.z * swr[(k0 + 2) * 2 + 1] + hv.w * swr[(k0 + 3) * 2 + 1];
    }
#pragma unroll
    for (int o = 16; o > 0; o >>= 1) {
        acc0 += __shfl_down_sync(0xffffffffu, acc0, o);
        acc1 += __shfl_down_sync(0xffffffffu, acc1, o);
    }
    if (lane == 0) {
        float v0 = acc0 + b2[0];
        float v1 = acc1 + b2[1];
        out[warp * 2 + 0] = 1.0f / (1.0f + __expf(-v0));
        out[warp * 2 + 1] = 1.0f / (1.0f + __expf(-v1));
    }
}

// ---------------- launch -----------------------------------------------------
extern "C" void kernel_launch(void* const* d_in, const int* in_sizes, int n_in,
                              void* d_out, int out_size) {
    const float* x   = (const float*)d_in[0];
    const int*   ei  = (const int*)d_in[1];
    const float* W1l = (const float*)d_in[2];
    const float* W1r = (const float*)d_in[3];
    const float* b1  = (const float*)d_in[4];
    const float* W2l = (const float*)d_in[5];
    const float* W2r = (const float*)d_in[6];
    const float* b2  = (const float*)d_in[7];

    float* out = (float*)d_out;
    float* emb = out + (size_t)N_NODES * N_CLASSES;  // embeddings region

    const int* src = ei;
    const int* dst = ei + N_EDGES;

    // CSR build (reused by both layers)
    k_zero_deg<<<(N_NODES + 255) / 256, 256>>>();
    k_hist<<<(N_EDGES + 255) / 256, 256>>>(dst);
    k_scan<<<1, 1024>>>();
    k_scatter<<<(N_EDGES + 255) / 256, 256>>>(src, dst);

    // layer 1
    k_agg1<<<(N_NODES + 7) / 8, 256>>>(x);
    dim3 g1((N_NODES + 63) / 64, HIDDEN / 64);
    k_gemm1<<<g1, 256>>>(x, W1l, W1r, b1, emb);

    // layer 2
    k_agg2<<<(N_NODES + 7) / 8, 256>>>(emb);
    k_out<<<(N_NODES + 7) / 8, 256>>>(W2l, W2r, b2, emb, out);
}

// round 4
// speedup vs baseline: 1.7807x; 1.7807x over previous
#include <cuda_runtime.h>
#include <cuda_bf16.h>
#include <cstdint>

#define N_NODES   50000
#define N_EDGES   800000
#define D_FEAT    128
#define HIDDEN    256
#define N_PAD     50048          // 391 * 128
#define M_TILES   391

// ---------------- scratch (static device globals) ---------------------------
__device__ int   g_deg[N_NODES];
__device__ int   g_rowptr[N_NODES + 1];
__device__ int   g_cursor[N_NODES];
__device__ float g_invdeg[N_NODES];
__device__ int   g_nbr[N_EDGES];
__device__ __nv_bfloat16 g_Ahi[(size_t)N_PAD * 256];   // [mean|x] hi; pad rows stay 0
__device__ __nv_bfloat16 g_Alo[(size_t)N_PAD * 256];
__device__ __nv_bfloat16 g_Bhi[256 * 256];             // B^T: [n][k], k-major
__device__ __nv_bfloat16 g_Blo[256 * 256];
__device__ float g_p[N_NODES * 2];   // h @ W2l (atomic-accumulated)
__device__ float g_q[N_NODES * 2];   // h @ W2r
__device__ float2 g_mp[N_NODES];     // mean over edges of g_p

// ---------------- CSR build --------------------------------------------------
__global__ void k_zero_deg() {
    int i = blockIdx.x * blockDim.x + threadIdx.x;
    if (i < N_NODES) g_deg[i] = 0;
}
__global__ void k_zero_pq() {
    int i = blockIdx.x * blockDim.x + threadIdx.x;
    if (i < N_NODES * 2) { g_p[i] = 0.f; g_q[i] = 0.f; }
}
__global__ void k_hist(const int* __restrict__ dst) {
    int e = blockIdx.x * blockDim.x + threadIdx.x;
    if (e < N_EDGES) atomicAdd(&g_deg[dst[e]], 1);
}
__global__ void k_scan() {
    __shared__ int warp_tot[32];
    __shared__ int s_carry;
    int tid = threadIdx.x, lane = tid & 31, wid = tid >> 5;
    if (tid == 0) s_carry = 0;
    __syncthreads();
    for (int base = 0; base < N_NODES; base += 1024) {
        int i = base + tid;
        int v = (i < N_NODES) ? g_deg[i] : 0;
        int xv = v;
#pragma unroll
        for (int o = 1; o < 32; o <<= 1) {
            int t = __shfl_up_sync(0xffffffffu, xv, o);
            if (lane >= o) xv += t;
        }
        if (lane == 31) warp_tot[wid] = xv;
        __syncthreads();
        if (wid == 0) {
            int w = warp_tot[lane];
#pragma unroll
            for (int o = 1; o < 32; o <<= 1) {
                int t = __shfl_up_sync(0xffffffffu, w, o);
                if (lane >= o) w += t;
            }
            warp_tot[lane] = w;
        }
        __syncthreads();
        int warp_off = (wid > 0) ? warp_tot[wid - 1] : 0;
        int excl = xv - v + warp_off + s_carry;
        if (i < N_NODES) {
            g_rowptr[i] = excl;
            g_cursor[i] = excl;
            g_invdeg[i] = 1.0f / (float)(v > 0 ? v : 1);
        }
        __syncthreads();
        if (tid == 1023) s_carry += warp_tot[31];
        __syncthreads();
    }
    if (threadIdx.x == 0) g_rowptr[N_NODES] = s_carry;
}
__global__ void k_scatter(const int* __restrict__ src, const int* __restrict__ dst) {
    int e = blockIdx.x * blockDim.x + threadIdx.x;
    if (e < N_EDGES) {
        int d = dst[e];
        int pos = atomicAdd(&g_cursor[d], 1);
        g_nbr[pos] = src[e];
    }
}

// ---------------- bf16 split helpers ----------------------------------------
__device__ __forceinline__ void split_bf16(float v, unsigned short& h, unsigned short& l) {
    __nv_bfloat16 bh = __float2bfloat16_rn(v);
    float r = v - __bfloat162float(bh);
    __nv_bfloat16 bl = __float2bfloat16_rn(r);
    h = __bfloat16_as_ushort(bh);
    l = __bfloat16_as_ushort(bl);
}

// agg layer1 (warp/node) + convert mean to bf16 hi/lo into A cols [0,128)
__global__ void k_agg1c(const float* __restrict__ x) {
    int warp = (blockIdx.x * blockDim.x + threadIdx.x) >> 5;
    int lane = threadIdx.x & 31;
    if (warp >= N_NODES) return;
    int beg = g_rowptr[warp], end = g_rowptr[warp + 1];
    float4 acc = make_float4(0.f, 0.f, 0.f, 0.f);
    for (int j = beg; j < end; j++) {
        int s = g_nbr[j];
        float4 v = *(const float4*)(x + (size_t)s * D_FEAT + lane * 4);
        acc.x += v.x; acc.y += v.y; acc.z += v.z; acc.w += v.w;
    }
    float id = g_invdeg[warp];
    acc.x *= id; acc.y *= id; acc.z *= id; acc.w *= id;
    unsigned short h0, h1, h2, h3, l0, l1, l2, l3;
    split_bf16(acc.x, h0, l0); split_bf16(acc.y, h1, l1);
    split_bf16(acc.z, h2, l2); split_bf16(acc.w, h3, l3);
    uint2 ph, pl;
    ph.x = (uint32_t)h0 | ((uint32_t)h1 << 16);
    ph.y = (uint32_t)h2 | ((uint32_t)h3 << 16);
    pl.x = (uint32_t)l0 | ((uint32_t)l1 << 16);
    pl.y = (uint32_t)l2 | ((uint32_t)l3 << 16);
    size_t off = (size_t)warp * 256 + lane * 4;
    *reinterpret_cast<uint2*>(&g_Ahi[off]) = ph;
    *reinterpret_cast<uint2*>(&g_Alo[off]) = pl;
}

// convert x into A cols [128,256)
__global__ void k_convx(const float* __restrict__ x) {
    int i = blockIdx.x * blockDim.x + threadIdx.x;
    if (i >= N_NODES * 32) return;
    int node = i >> 5, lane = i & 31;
    float4 v = *(const float4*)(x + (size_t)node * D_FEAT + lane * 4);
    unsigned short h0, h1, h2, h3, l0, l1, l2, l3;
    split_bf16(v.x, h0, l0); split_bf16(v.y, h1, l1);
    split_bf16(v.z, h2, l2); split_bf16(v.w, h3, l3);
    uint2 ph, pl;
    ph.x = (uint32_t)h0 | ((uint32_t)h1 << 16);
    ph.y = (uint32_t)h2 | ((uint32_t)h3 << 16);
    pl.x = (uint32_t)l0 | ((uint32_t)l1 << 16);
    pl.y = (uint32_t)l2 | ((uint32_t)l3 << 16);
    size_t off = (size_t)node * 256 + 128 + lane * 4;
    *reinterpret_cast<uint2*>(&g_Ahi[off]) = ph;
    *reinterpret_cast<uint2*>(&g_Alo[off]) = pl;
}

// B^T build: g_B[n][k] = W1[k][n], W1 = [W1l ; W1r]
__global__ void k_convW(const float* __restrict__ W1l, const float* __restrict__ W1r) {
    int i = blockIdx.x * blockDim.x + threadIdx.x;
    if (i >= 256 * 256) return;
    int k = i >> 8, n = i & 255;
    float v = (k < 128) ? W1l[k * 256 + n] : W1r[(k - 128) * 256 + n];
    unsigned short h, l;
    split_bf16(v, h, l);
    g_Bhi[n * 256 + k] = __ushort_as_bfloat16(h);
    g_Blo[n * 256 + k] = __ushort_as_bfloat16(l);
}

// ---------------- HMMA GEMM1 + fused layer-2 projections ---------------------
// block tile 128(M) x 128(N), 8 warps = 4(M) x 2(N), warp tile 32x64
// K loop: 4 chunks of 64. smem stride: 72 halves (144B) per row.
#define SA_HI   0
#define SA_LO   18432
#define SB_HI   36864
#define SB_LO   55296
#define SBIAS   73728     // 128 f32
#define SW2L    74240     // 128 float2
#define SW2R    75264     // 128 float2
#define SM_TOT  76288

__device__ __forceinline__ void mma_bf16(float* d, const uint32_t* a,
                                         uint32_t b0, uint32_t b1) {
    asm volatile(
        "mma.sync.aligned.m16n8k16.row.col.f32.bf16.bf16.f32 "
        "{%0,%1,%2,%3}, {%4,%5,%6,%7}, {%8,%9}, {%0,%1,%2,%3};"
        : "+f"(d[0]), "+f"(d[1]), "+f"(d[2]), "+f"(d[3])
        : "r"(a[0]), "r"(a[1]), "r"(a[2]), "r"(a[3]), "r"(b0), "r"(b1));
}

__global__ void __launch_bounds__(256, 1)
k_gemm1_mma(const float* __restrict__ b1,
            const float* __restrict__ W2l, const float* __restrict__ W2r,
            float* __restrict__ h) {
    extern __shared__ char smem[];
    int tid  = threadIdx.x, lane = tid & 31, warp = tid >> 5;
    int warpM = warp & 3, warpN = warp >> 2;
    int m0 = blockIdx.x * 128, n0 = blockIdx.y * 128;

    float*  bias = (float*)(smem + SBIAS);
    float2* w2l  = (float2*)(smem + SW2L);
    float2* w2r  = (float2*)(smem + SW2R);
    if (tid < 128) {
        bias[tid] = b1[n0 + tid];
        w2l[tid]  = ((const float2*)W2l)[n0 + tid];
        w2r[tid]  = ((const float2*)W2r)[n0 + tid];
    }

    float acc[2][8][4];
#pragma unroll
    for (int mt = 0; mt < 2; mt++)
#pragma unroll
        for (int nt = 0; nt < 8; nt++)
#pragma unroll
            for (int j = 0; j < 4; j++) acc[mt][nt][j] = 0.f;

#pragma unroll 1
    for (int c = 0; c < 4; c++) {
        __syncthreads();
#pragma unroll
        for (int t = 0; t < 4; t++) {
            int idx = tid + t * 256;
            int r = idx >> 3, q = idx & 7;
            size_t ga = (size_t)(m0 + r) * 256 + c * 64 + q * 8;
            size_t gb = (size_t)(n0 + r) * 256 + c * 64 + q * 8;
            uint32_t so = (uint32_t)(r * 144 + q * 16);
            *(uint4*)(smem + SA_HI + so) = *(const uint4*)(g_Ahi + ga);
            *(uint4*)(smem + SA_LO + so) = *(const uint4*)(g_Alo + ga);
            *(uint4*)(smem + SB_HI + so) = *(const uint4*)(g_Bhi + gb);
            *(uint4*)(smem + SB_LO + so) = *(const uint4*)(g_Blo + gb);
        }
        __syncthreads();
#pragma unroll
        for (int s = 0; s < 4; s++) {
            int kb = s * 16 + (lane & 3) * 2;       // lane's first k element
            int ar = warpM * 32 + (lane >> 2);
            uint32_t ah[2][4], al[2][4];
#pragma unroll
            for (int mt = 0; mt < 2; mt++) {
                int r0 = ar + mt * 16;
                uint32_t o00 = (uint32_t)(r0 * 144 + kb * 2);
                uint32_t o10 = o00 + 8 * 144;
                ah[mt][0] = *(const uint32_t*)(smem + SA_HI + o00);
                ah[mt][1] = *(const uint32_t*)(smem + SA_HI + o10);
                ah[mt][2] = *(const uint32_t*)(smem + SA_HI + o00 + 16);
                ah[mt][3] = *(const uint32_t*)(smem + SA_HI + o10 + 16);
                al[mt][0] = *(const uint32_t*)(smem + SA_LO + o00);
                al[mt][1] = *(const uint32_t*)(smem + SA_LO + o10);
                al[mt][2] = *(const uint32_t*)(smem + SA_LO + o00 + 16);
                al[mt][3] = *(const uint32_t*)(smem + SA_LO + o10 + 16);
            }
#pragma unroll
            for (int nt = 0; nt < 8; nt++) {
                int bn = warpN * 64 + nt * 8 + (lane >> 2);
                uint32_t bo = (uint32_t)(bn * 144 + kb * 2);
                uint32_t bh0 = *(const uint32_t*)(smem + SB_HI + bo);
                uint32_t bh1 = *(const uint32_t*)(smem + SB_HI + bo + 16);
                uint32_t bl0 = *(const uint32_t*)(smem + SB_LO + bo);
                uint32_t bl1 = *(const uint32_t*)(smem + SB_LO + bo + 16);
#pragma unroll
                for (int mt = 0; mt < 2; mt++) {
                    mma_bf16(acc[mt][nt], ah[mt], bh0, bh1);
                    mma_bf16(acc[mt][nt], ah[mt], bl0, bl1);
                    mma_bf16(acc[mt][nt], al[mt], bh0, bh1);
                }
            }
        }
    }

    // epilogue: bias + relu + store h; fused projections p = h@W2l, q = h@W2r
#pragma unroll
    for (int mt = 0; mt < 2; mt++) {
        int rowA = m0 + warpM * 32 + mt * 16 + (lane >> 2);
        int rowB = rowA + 8;
        float pla0 = 0.f, pla1 = 0.f, pra0 = 0.f, pra1 = 0.f;
        float plb0 = 0.f, plb1 = 0.f, prb0 = 0.f, prb1 = 0.f;
#pragma unroll
        for (int nt = 0; nt < 8; nt++) {
            int cl = warpN * 64 + nt * 8 + (lane & 3) * 2;  // local col 0..127
            float bz0 = bias[cl], bz1 = bias[cl + 1];
            float h0 = fmaxf(acc[mt][nt][0] + bz0, 0.f);
            float h1 = fmaxf(acc[mt][nt][1] + bz1, 0.f);
            float h2 = fmaxf(acc[mt][nt][2] + bz0, 0.f);
            float h3 = fmaxf(acc[mt][nt][3] + bz1, 0.f);
            if (rowA < N_NODES)
                *(float2*)(h + (size_t)rowA * 256 + n0 + cl) = make_float2(h0, h1);
            if (rowB < N_NODES)
                *(float2*)(h + (size_t)rowB * 256 + n0 + cl) = make_float2(h2, h3);
            float2 wl0 = w2l[cl], wl1 = w2l[cl + 1];
            float2 wr0 = w2r[cl], wr1 = w2r[cl + 1];
            pla0 += h0 * wl0.x + h1 * wl1.x;  pla1 += h0 * wl0.y + h1 * wl1.y;
            pra0 += h0 * wr0.x + h1 * wr1.x;  pra1 += h0 * wr0.y + h1 * wr1.y;
            plb0 += h2 * wl0.x + h3 * wl1.x;  plb1 += h2 * wl0.y + h3 * wl1.y;
            prb0 += h2 * wr0.x + h3 * wr1.x;  prb1 += h2 * wr0.y + h3 * wr1.y;
        }
#pragma unroll
        for (int o = 1; o <= 2; o <<= 1) {
            pla0 += __shfl_xor_sync(0xffffffffu, pla0, o);
            pla1 += __shfl_xor_sync(0xffffffffu, pla1, o);
            pra0 += __shfl_xor_sync(0xffffffffu, pra0, o);
            pra1 += __shfl_xor_sync(0xffffffffu, pra1, o);
            plb0 += __shfl_xor_sync(0xffffffffu, plb0, o);
            plb1 += __shfl_xor_sync(0xffffffffu, plb1, o);
            prb0 += __shfl_xor_sync(0xffffffffu, prb0, o);
            prb1 += __shfl_xor_sync(0xffffffffu, prb1, o);
        }
        if ((lane & 3) == 0) {
            if (rowA < N_NODES) {
                atomicAdd(&g_p[rowA * 2 + 0], pla0);
                atomicAdd(&g_p[rowA * 2 + 1], pla1);
                atomicAdd(&g_q[rowA * 2 + 0], pra0);
                atomicAdd(&g_q[rowA * 2 + 1], pra1);
            }
            if (rowB < N_NODES) {
                atomicAdd(&g_p[rowB * 2 + 0], plb0);
                atomicAdd(&g_p[rowB * 2 + 1], plb1);
                atomicAdd(&g_q[rowB * 2 + 0], prb0);
                atomicAdd(&g_q[rowB * 2 + 1], prb1);
            }
        }
    }
}

// ---------------- layer-2 aggregation (8B/edge) + output ---------------------
__global__ void k_aggp() {
    int i = blockIdx.x * blockDim.x + threadIdx.x;
    if (i >= N_NODES) return;
    int beg = g_rowptr[i], end = g_rowptr[i + 1];
    float a0 = 0.f, a1 = 0.f;
    const float2* p2 = (const float2*)g_p;
    for (int j = beg; j < end; j++) {
        float2 v = p2[g_nbr[j]];
        a0 += v.x; a1 += v.y;
    }
    float id = g_invdeg[i];
    g_mp[i] = make_float2(a0 * id, a1 * id);
}

__global__ void k_out2(const float* __restrict__ b2, float* __restrict__ out) {
    int i = blockIdx.x * blockDim.x + threadIdx.x;
    if (i >= N_NODES) return;
    float2 mp = g_mp[i];
    float v0 = mp.x + g_q[i * 2 + 0] + b2[0];
    float v1 = mp.y + g_q[i * 2 + 1] + b2[1];
    out[i * 2 + 0] = 1.0f / (1.0f + __expf(-v0));
    out[i * 2 + 1] = 1.0f / (1.0f + __expf(-v1));
}

// ---------------- launch ------------------------------------------------------
extern "C" void kernel_launch(void* const* d_in, const int* in_sizes, int n_in,
                              void* d_out, int out_size) {
    const float* x   = (const float*)d_in[0];
    const int*   ei  = (const int*)d_in[1];
    const float* W1l = (const float*)d_in[2];
    const float* W1r = (const float*)d_in[3];
    const float* b1  = (const float*)d_in[4];
    const float* W2l = (const float*)d_in[5];
    const float* W2r = (const float*)d_in[6];
    const float* b2  = (const float*)d_in[7];

    float* out = (float*)d_out;
    float* emb = out + (size_t)N_NODES * 2;

    const int* src = ei;
    const int* dst = ei + N_EDGES;

    cudaFuncSetAttribute(k_gemm1_mma, cudaFuncAttributeMaxDynamicSharedMemorySize, SM_TOT);

    // weight/feature conversion (independent of CSR)
    k_convW<<<(256 * 256 + 255) / 256, 256>>>(W1l, W1r);
    k_convx<<<(N_NODES * 32 + 255) / 256, 256>>>(x);
    k_zero_pq<<<(N_NODES * 2 + 255) / 256, 256>>>();

    // CSR build
    k_zero_deg<<<(N_NODES + 255) / 256, 256>>>();
    k_hist<<<(N_EDGES + 255) / 256, 256>>>(dst);
    k_scan<<<1, 1024>>>();
    k_scatter<<<(N_EDGES + 255) / 256, 256>>>(src, dst);

    // layer 1 aggregation + A conversion
    k_agg1c<<<(N_NODES + 7) / 8, 256>>>(x);

    // layer-1 GEMM (HMMA) + fused layer-2 projections
    dim3 g1(M_TILES, 2);
    k_gemm1_mma<<<g1, 256, SM_TOT>>>(b1, W2l, W2r, emb);

    // layer-2: aggregate 2-dim projections, then output
    k_aggp<<<(N_NODES + 255) / 256, 256>>>();
    k_out2<<<(N_NODES + 255) / 256, 256>>>(b2, out);
}